// round 10
// baseline (speedup 1.0000x reference)
#include <cuda_runtime.h>
#include <cuda_fp16.h>

#define RES    512
#define FEAT   32
#define NPLANE 6
#define PAIRS  (FEAT / 2)   // 16 half2 per texel

// Channel-last fp16 scratch: [6][512][512][16] half2 = 100.7 MB.
__device__ __half2 g_scratch[(size_t)NPLANE * RES * RES * PAIRS];

// Completion counter for transpose{2,4,5} CTAs inside the fused kernel.
__device__ unsigned int g_t245_done;

// K1: transpose {0,1,3}, 4-row tiles: 16 wtiles x 128 hgroups x 3 = 6144 blocks
#define TB1 6144
// Fused kernel: transpose {2,4,5}, 2-row tiles: 16 x 256 x 3 = 12288 blocks,
// interleaved with S0 via a mod-9 pattern (4 transpose : 5 sample).
#define TB2        12288
#define B_SPLIT    27648      // (TB2/4)*9
#define SB_PATTERN 15360      // (B_SPLIT/9)*5

// ---------------------------------------------------------------------------
// Transpose tile body: 256 threads (tx 0..31, ty 0..7), ROWS h-rows, 32 chans.
// Loads staged to registers, then smem; writes 128B contiguous per warp/row.
// ---------------------------------------------------------------------------
template<int P0, int P1, int P2, int ROWS>
__device__ __forceinline__ void transpose_body(const float* __restrict__ planes,
                                               int tb) {
    __shared__ float t[ROWS][32][33];

    const int tx = threadIdx.x & 31;
    const int ty = threadIdx.x >> 5;              // 0..7

    constexpr int HG = RES / ROWS;
    const int wt = tb & 15;
    const int hb = ((tb >> 4) % HG) * ROWS;
    const int pj = tb / (16 * HG);                // 0..2
    const int p  = (pj == 0) ? P0 : (pj == 1) ? P1 : P2;

    const size_t cs = (size_t)RES * RES;
    const float* __restrict__ src =
        planes + ((size_t)p * FEAT + ty) * cs + (size_t)hb * RES + (wt * 32 + tx);

    float v[ROWS][4];
    #pragma unroll
    for (int r = 0; r < ROWS; ++r)
        #pragma unroll
        for (int c = 0; c < 4; ++c)
            v[r][c] = __ldcs(src + (size_t)r * RES + (size_t)(8 * c) * cs);

    #pragma unroll
    for (int r = 0; r < ROWS; ++r)
        #pragma unroll
        for (int c = 0; c < 4; ++c)
            t[r][ty + 8 * c][tx] = v[r][c];
    __syncthreads();

    const int pair = tx & 15;
    #pragma unroll
    for (int r = 0; r < ROWS; ++r) {
        #pragma unroll
        for (int j = 0; j < 2; ++j) {
            const int wl  = (ty + 8 * j) * 2 + (tx >> 4);   // 0..31
            const int col = wt * 32 + wl;
            g_scratch[(((p * RES + (hb + r)) * RES) + col) * PAIRS + pair] =
                __floats2half2_rn(t[r][2 * pair][wl], t[r][2 * pair + 1][wl]);
        }
    }
}

// ---------------------------------------------------------------------------
// Sample body: warp covers 8 points, 2 points/thread, 24 batched 8B gathers.
// G=0: planes {0,1,3} -> space. G=1: {2,4,5} -> spacetime.
// ---------------------------------------------------------------------------
template<int G>
__device__ __forceinline__ void sample_body(const float* __restrict__ pts,
                                            const float* __restrict__ tim,
                                            float* __restrict__ out,
                                            int N, int sbid) {
    const int gwarp = (sbid * 256 + (int)threadIdx.x) >> 5;
    const int lane  = threadIdx.x & 31;
    const int sub   = lane & 7;
    const int k     = lane >> 3;

    const int wpt = gwarp * 8;
    if (wpt >= N) return;

    int ptv[2];
    ptv[0] = wpt + k;
    ptv[1] = wpt + k + 4;

    const __half2* __restrict__ sc = g_scratch;

    int   a00[2][3], a01[2][3], a10[2][3], a11[2][3];
    float w00[2][3], w01[2][3], w10[2][3], w11[2][3];
    bool  valid[2];

    #pragma unroll
    for (int q = 0; q < 2; ++q) {
        const int pt = ptv[q];
        valid[q] = (pt < N);
        const int ps = valid[q] ? pt : 0;

        const float inv_b = 1.0f / 1.6f;
        const float dx = pts[ps * 3 + 0] * inv_b;
        const float dy = pts[ps * 3 + 1] * inv_b;
        const float dz = pts[ps * 3 + 2] * inv_b;

        float cx[3], cy[3];
        int pid[3];
        if (G == 0) {
            pid[0] = 0; cx[0] = dx; cy[0] = dy;
            pid[1] = 1; cx[1] = dx; cy[1] = dz;
            pid[2] = 3; cx[2] = dy; cy[2] = dz;
        } else {
            const float dt = tim[ps] * 2.0f - 1.0f;
            pid[0] = 2; cx[0] = dt; cy[0] = dx;
            pid[1] = 4; cx[1] = dt; cy[1] = dy;
            pid[2] = 5; cx[2] = dt; cy[2] = dz;
        }

        #pragma unroll
        for (int i = 0; i < 3; ++i) {
            const float x = fminf(fmaxf((cx[i] + 1.0f) * 0.5f * (float)(RES - 1), 0.0f), (float)(RES - 1));
            const float y = fminf(fmaxf((cy[i] + 1.0f) * 0.5f * (float)(RES - 1), 0.0f), (float)(RES - 1));
            const float x0f = floorf(x);
            const float y0f = floorf(y);
            const int x0 = (int)x0f;
            const int y0 = (int)y0f;
            const int x1 = min(x0 + 1, RES - 1);
            const int y1 = min(y0 + 1, RES - 1);
            const float wx = x - x0f;
            const float wy = y - y0f;

            const int pbase = pid[i] * (RES * RES * PAIRS) + 2 * sub;
            a00[q][i] = pbase + (y0 * RES + x0) * PAIRS;
            a01[q][i] = pbase + (y0 * RES + x1) * PAIRS;
            a10[q][i] = pbase + (y1 * RES + x0) * PAIRS;
            a11[q][i] = pbase + (y1 * RES + x1) * PAIRS;
            w00[q][i] = (1.0f - wx) * (1.0f - wy);
            w01[q][i] = wx * (1.0f - wy);
            w10[q][i] = (1.0f - wx) * wy;
            w11[q][i] = wx * wy;
        }
    }

    uint2 c00[2][3], c01[2][3], c10[2][3], c11[2][3];
    #pragma unroll
    for (int q = 0; q < 2; ++q) {
        #pragma unroll
        for (int i = 0; i < 3; ++i) {
            c00[q][i] = __ldg((const uint2*)(sc + a00[q][i]));
            c01[q][i] = __ldg((const uint2*)(sc + a01[q][i]));
            c10[q][i] = __ldg((const uint2*)(sc + a10[q][i]));
            c11[q][i] = __ldg((const uint2*)(sc + a11[q][i]));
        }
    }

    #pragma unroll
    for (int q = 0; q < 2; ++q) {
        float f[3][4];
        #pragma unroll
        for (int i = 0; i < 3; ++i) {
            const float2 v00a = __half22float2(*(const __half2*)&c00[q][i].x);
            const float2 v00b = __half22float2(*(const __half2*)&c00[q][i].y);
            const float2 v01a = __half22float2(*(const __half2*)&c01[q][i].x);
            const float2 v01b = __half22float2(*(const __half2*)&c01[q][i].y);
            const float2 v10a = __half22float2(*(const __half2*)&c10[q][i].x);
            const float2 v10b = __half22float2(*(const __half2*)&c10[q][i].y);
            const float2 v11a = __half22float2(*(const __half2*)&c11[q][i].x);
            const float2 v11b = __half22float2(*(const __half2*)&c11[q][i].y);

            f[i][0] = v00a.x * w00[q][i] + v01a.x * w01[q][i] + v10a.x * w10[q][i] + v11a.x * w11[q][i];
            f[i][1] = v00a.y * w00[q][i] + v01a.y * w01[q][i] + v10a.y * w10[q][i] + v11a.y * w11[q][i];
            f[i][2] = v00b.x * w00[q][i] + v01b.x * w01[q][i] + v10b.x * w10[q][i] + v11b.x * w11[q][i];
            f[i][3] = v00b.y * w00[q][i] + v01b.y * w01[q][i] + v10b.y * w10[q][i] + v11b.y * w11[q][i];
        }

        float4 r;
        r.x = f[0][0] * f[1][0] * f[2][0];
        r.y = f[0][1] * f[1][1] * f[2][1];
        r.z = f[0][2] * f[1][2] * f[2][2];
        r.w = f[0][3] * f[1][3] * f[2][3];

        if (valid[q]) {
            float4* __restrict__ o = (float4*)out + (size_t)G * N * 8 + (size_t)ptv[q] * 8 + sub;
            __stcs(o, r);
        }
    }
}

// K1: transpose planes {0,1,3}; also resets the dependency counter.
__global__ void __launch_bounds__(256)
transpose_first_kernel(const float* __restrict__ planes) {
    if (blockIdx.x == 0 && threadIdx.x == 0) g_t245_done = 0u;
    transpose_body<0, 1, 3, 4>(planes, blockIdx.x);
}

// Fused kernel:
//   bid < B_SPLIT:              r=bid%9; r<4 -> transpose{2,4,5} tile (bid/9)*4+r
//                                        else -> S0 block (bid/9)*5+(r-4)
//   B_SPLIT <= bid < B_SPLIT+extra: S0 block SB_PATTERN + (bid - B_SPLIT)
//   bid >= B_SPLIT+extra:       S1 block; spins until all TB2 transpose CTAs done.
__global__ void __launch_bounds__(256)
fused_kernel(const float* __restrict__ planes,
             const float* __restrict__ pts,
             const float* __restrict__ tim,
             float* __restrict__ out,
             int N, int extra) {
    const int bid = blockIdx.x;
    if (bid < B_SPLIT) {
        const int q = bid / 9;
        const int r = bid % 9;
        if (r < 4) {
            transpose_body<2, 4, 5, 2>(planes, q * 4 + r);
            // Publish completion: order this CTA's stores, then count.
            __threadfence();
            __syncthreads();
            if (threadIdx.x == 0) atomicAdd(&g_t245_done, 1u);
        } else {
            sample_body<0>(pts, tim, out, N, q * 5 + (r - 4));
        }
    } else if (bid < B_SPLIT + extra) {
        sample_body<0>(pts, tim, out, N, SB_PATTERN + (bid - B_SPLIT));
    } else {
        // S1: wait for all transpose{2,4,5} CTAs (normally already complete
        // by the time these high-bid CTAs are scheduled).
        if (threadIdx.x == 0) {
            while (atomicAdd(&g_t245_done, 0u) != (unsigned)TB2) __nanosleep(200);
        }
        __syncthreads();
        __threadfence();
        sample_body<1>(pts, tim, out, N, bid - B_SPLIT - extra);
    }
}

extern "C" void kernel_launch(void* const* d_in, const int* in_sizes, int n_in,
                              void* d_out, int out_size) {
    const float* pts    = (const float*)d_in[0];
    const float* tim    = (const float*)d_in[1];
    const float* planes = (const float*)d_in[2];

    const int N = in_sizes[0] / 3;

    const int warps   = (N + 7) / 8;
    const int sblocks = (warps * 32 + 255) / 256;

    transpose_first_kernel<<<TB1, 256>>>(planes);

    int extra = sblocks - SB_PATTERN;
    if (extra < 0) extra = 0;
    const int grid = B_SPLIT + extra + sblocks;
    fused_kernel<<<grid, 256>>>(planes, pts, tim, (float*)d_out, N, extra);
}

// round 11
// speedup vs baseline: 1.0598x; 1.0598x over previous
#include <cuda_runtime.h>
#include <cuda_fp16.h>

#define RES    512
#define FEAT   32
#define NPLANE 6
#define PAIRS  (FEAT / 2)   // 16 half2 per texel

// Channel-last fp16 scratch: [6][512][512][16] half2 = 100.7 MB.
__device__ __half2 g_scratch[(size_t)NPLANE * RES * RES * PAIRS];

// K1: transpose {0,1,3}, smem-free, ROWS=4: 8 wtiles x 128 hgroups x 3 = 3072 blocks
#define TB1 3072
// Fused: transpose {2,4,5}, smem-free, ROWS=2: 8 x 256 x 3 = 6144 blocks,
// interleaved 2:5 with S0 sampler blocks (mod-7 pattern).
#define B_SPLIT    21504      // (6144/2)*7
#define SB_PATTERN 15360      // (B_SPLIT/7)*5

// ---------------------------------------------------------------------------
// Smem-free transpose: each warp handles 32 channels x 8 w x ROWS rows.
// lane = (pair p 0..15, j 0..1). Loads: float4 from channels 2p,2p+1 at
// w0+4j (two lanes cover a full 32B sector per channel row). Stores: half2
// direct to scratch; per instruction the warp covers 2 x 64B full segments.
// No shared memory, no barriers.
// ---------------------------------------------------------------------------
template<int P0, int P1, int P2, int ROWS>
__device__ __forceinline__ void transpose_body(const float* __restrict__ planes,
                                               int tb) {
    const int lane = threadIdx.x & 31;
    const int wrp  = threadIdx.x >> 5;           // 0..7
    const int pair = lane & 15;
    const int j    = lane >> 4;                  // 0..1

    constexpr int HG = RES / ROWS;
    const int w0 = (tb & 7) * 64 + wrp * 8;      // 8 w-tiles of 64
    const int hb = ((tb >> 3) % HG) * ROWS;
    const int pj = tb / (8 * HG);                // 0..2
    const int p  = (pj == 0) ? P0 : (pj == 1) ? P1 : P2;

    const size_t cs = (size_t)RES * RES;
    const float* __restrict__ srcA =
        planes + ((size_t)p * FEAT + 2 * pair) * cs + (size_t)hb * RES + (w0 + 4 * j);
    const float* __restrict__ srcB = srcA + cs;

    // Stage all loads (2*ROWS independent 16B loads per thread).
    float4 a[ROWS], b[ROWS];
    #pragma unroll
    for (int r = 0; r < ROWS; ++r) {
        a[r] = __ldcs((const float4*)(srcA + (size_t)r * RES));
        b[r] = __ldcs((const float4*)(srcB + (size_t)r * RES));
    }

    #pragma unroll
    for (int r = 0; r < ROWS; ++r) {
        const int tex = w0 + 4 * j;
        __half2* __restrict__ dst =
            g_scratch + (((size_t)p * RES + (hb + r)) * RES + tex) * PAIRS + pair;
        dst[0 * PAIRS] = __floats2half2_rn(a[r].x, b[r].x);
        dst[1 * PAIRS] = __floats2half2_rn(a[r].y, b[r].y);
        dst[2 * PAIRS] = __floats2half2_rn(a[r].z, b[r].z);
        dst[3 * PAIRS] = __floats2half2_rn(a[r].w, b[r].w);
    }
}

// ---------------------------------------------------------------------------
// Sample body: warp covers 8 points, 2 points/thread, 24 batched 8B gathers.
// G=0: planes {0,1,3} -> space. G=1: {2,4,5} -> spacetime.
// ---------------------------------------------------------------------------
template<int G>
__device__ __forceinline__ void sample_body(const float* __restrict__ pts,
                                            const float* __restrict__ tim,
                                            float* __restrict__ out,
                                            int N, int sbid) {
    const int gwarp = (sbid * 256 + (int)threadIdx.x) >> 5;
    const int lane  = threadIdx.x & 31;
    const int sub   = lane & 7;
    const int k     = lane >> 3;

    const int wpt = gwarp * 8;
    if (wpt >= N) return;

    int ptv[2];
    ptv[0] = wpt + k;
    ptv[1] = wpt + k + 4;

    const __half2* __restrict__ sc = g_scratch;

    int   a00[2][3], a01[2][3], a10[2][3], a11[2][3];
    float w00[2][3], w01[2][3], w10[2][3], w11[2][3];
    bool  valid[2];

    #pragma unroll
    for (int q = 0; q < 2; ++q) {
        const int pt = ptv[q];
        valid[q] = (pt < N);
        const int ps = valid[q] ? pt : 0;

        const float inv_b = 1.0f / 1.6f;
        const float dx = pts[ps * 3 + 0] * inv_b;
        const float dy = pts[ps * 3 + 1] * inv_b;
        const float dz = pts[ps * 3 + 2] * inv_b;

        float cx[3], cy[3];
        int pid[3];
        if (G == 0) {
            pid[0] = 0; cx[0] = dx; cy[0] = dy;
            pid[1] = 1; cx[1] = dx; cy[1] = dz;
            pid[2] = 3; cx[2] = dy; cy[2] = dz;
        } else {
            const float dt = tim[ps] * 2.0f - 1.0f;
            pid[0] = 2; cx[0] = dt; cy[0] = dx;
            pid[1] = 4; cx[1] = dt; cy[1] = dy;
            pid[2] = 5; cx[2] = dt; cy[2] = dz;
        }

        #pragma unroll
        for (int i = 0; i < 3; ++i) {
            const float x = fminf(fmaxf((cx[i] + 1.0f) * 0.5f * (float)(RES - 1), 0.0f), (float)(RES - 1));
            const float y = fminf(fmaxf((cy[i] + 1.0f) * 0.5f * (float)(RES - 1), 0.0f), (float)(RES - 1));
            const float x0f = floorf(x);
            const float y0f = floorf(y);
            const int x0 = (int)x0f;
            const int y0 = (int)y0f;
            const int x1 = min(x0 + 1, RES - 1);
            const int y1 = min(y0 + 1, RES - 1);
            const float wx = x - x0f;
            const float wy = y - y0f;

            const int pbase = pid[i] * (RES * RES * PAIRS) + 2 * sub;
            a00[q][i] = pbase + (y0 * RES + x0) * PAIRS;
            a01[q][i] = pbase + (y0 * RES + x1) * PAIRS;
            a10[q][i] = pbase + (y1 * RES + x0) * PAIRS;
            a11[q][i] = pbase + (y1 * RES + x1) * PAIRS;
            w00[q][i] = (1.0f - wx) * (1.0f - wy);
            w01[q][i] = wx * (1.0f - wy);
            w10[q][i] = (1.0f - wx) * wy;
            w11[q][i] = wx * wy;
        }
    }

    uint2 c00[2][3], c01[2][3], c10[2][3], c11[2][3];
    #pragma unroll
    for (int q = 0; q < 2; ++q) {
        #pragma unroll
        for (int i = 0; i < 3; ++i) {
            c00[q][i] = __ldg((const uint2*)(sc + a00[q][i]));
            c01[q][i] = __ldg((const uint2*)(sc + a01[q][i]));
            c10[q][i] = __ldg((const uint2*)(sc + a10[q][i]));
            c11[q][i] = __ldg((const uint2*)(sc + a11[q][i]));
        }
    }

    #pragma unroll
    for (int q = 0; q < 2; ++q) {
        float f[3][4];
        #pragma unroll
        for (int i = 0; i < 3; ++i) {
            const float2 v00a = __half22float2(*(const __half2*)&c00[q][i].x);
            const float2 v00b = __half22float2(*(const __half2*)&c00[q][i].y);
            const float2 v01a = __half22float2(*(const __half2*)&c01[q][i].x);
            const float2 v01b = __half22float2(*(const __half2*)&c01[q][i].y);
            const float2 v10a = __half22float2(*(const __half2*)&c10[q][i].x);
            const float2 v10b = __half22float2(*(const __half2*)&c10[q][i].y);
            const float2 v11a = __half22float2(*(const __half2*)&c11[q][i].x);
            const float2 v11b = __half22float2(*(const __half2*)&c11[q][i].y);

            f[i][0] = v00a.x * w00[q][i] + v01a.x * w01[q][i] + v10a.x * w10[q][i] + v11a.x * w11[q][i];
            f[i][1] = v00a.y * w00[q][i] + v01a.y * w01[q][i] + v10a.y * w10[q][i] + v11a.y * w11[q][i];
            f[i][2] = v00b.x * w00[q][i] + v01b.x * w01[q][i] + v10b.x * w10[q][i] + v11b.x * w11[q][i];
            f[i][3] = v00b.y * w00[q][i] + v01b.y * w01[q][i] + v10b.y * w10[q][i] + v11b.y * w11[q][i];
        }

        float4 r;
        r.x = f[0][0] * f[1][0] * f[2][0];
        r.y = f[0][1] * f[1][1] * f[2][1];
        r.z = f[0][2] * f[1][2] * f[2][2];
        r.w = f[0][3] * f[1][3] * f[2][3];

        if (valid[q]) {
            float4* __restrict__ o = (float4*)out + (size_t)G * N * 8 + (size_t)ptv[q] * 8 + sub;
            __stcs(o, r);
        }
    }
}

// K1: transpose planes {0,1,3}, smem-free, 4-row tiles.
__global__ void __launch_bounds__(256)
transpose_first_kernel(const float* __restrict__ planes) {
    transpose_body<0, 1, 3, 4>(planes, blockIdx.x);
}

// K2: role-interleaved fused kernel (smem = 0 for all CTAs).
//   bid < B_SPLIT: r=bid%7; r<2 -> transpose{2,4,5} tile (bid/7)*2+r
//                           else -> sample0 block (bid/7)*5+(r-2)
//   bid >= B_SPLIT: sample0 block SB_PATTERN + (bid - B_SPLIT)
__global__ void __launch_bounds__(256)
fused_kernel(const float* __restrict__ planes,
             const float* __restrict__ pts,
             const float* __restrict__ tim,
             float* __restrict__ out,
             int N) {
    const int bid = blockIdx.x;
    if (bid < B_SPLIT) {
        const int q = bid / 7;
        const int r = bid % 7;
        if (r < 2) {
            transpose_body<2, 4, 5, 2>(planes, q * 2 + r);
        } else {
            sample_body<0>(pts, tim, out, N, q * 5 + (r - 2));
        }
    } else {
        sample_body<0>(pts, tim, out, N, SB_PATTERN + (bid - B_SPLIT));
    }
}

// K3: sample group 1.
__global__ void __launch_bounds__(256)
sample1_kernel(const float* __restrict__ pts,
               const float* __restrict__ tim,
               float* __restrict__ out,
               int N) {
    sample_body<1>(pts, tim, out, N, blockIdx.x);
}

extern "C" void kernel_launch(void* const* d_in, const int* in_sizes, int n_in,
                              void* d_out, int out_size) {
    const float* pts    = (const float*)d_in[0];
    const float* tim    = (const float*)d_in[1];
    const float* planes = (const float*)d_in[2];

    const int N = in_sizes[0] / 3;

    const int warps   = (N + 7) / 8;
    const int sblocks = (warps * 32 + 255) / 256;

    transpose_first_kernel<<<TB1, 256>>>(planes);

    int extra = sblocks - SB_PATTERN;
    if (extra < 0) extra = 0;
    fused_kernel<<<B_SPLIT + extra, 256>>>(planes, pts, tim, (float*)d_out, N);

    sample1_kernel<<<sblocks, 256>>>(pts, tim, (float*)d_out, N);
}

// round 12
// speedup vs baseline: 1.1237x; 1.0603x over previous
#include <cuda_runtime.h>
#include <cuda_fp16.h>

#define RES    512
#define FEAT   32
#define NPLANE 6
#define PAIRS  (FEAT / 2)   // 16 half2 per texel

// Channel-last fp16 scratch: [6][512][512][16] half2 = 100.7 MB.
__device__ __half2 g_scratch[(size_t)NPLANE * RES * RES * PAIRS];

// K1: transpose {0,1,3}, 4-row tiles: 16 wtiles x 128 hgroups x 3 = 6144 blocks
#define TB1 6144
// Fused K2: transpose {2,4,5}, 2-row tiles: 16 x 256 x 3 = 12288 blocks,
// interleaved with samplers via a mod-9 pattern (4 transpose : 5 sample).
#define TB2        12288
#define B_SPLIT    27648      // (TB2/4)*9
#define SB_PATTERN 15360      // (B_SPLIT/9)*5

// ---------------------------------------------------------------------------
// Transpose tile body (R8 backbone): 256 threads, ROWS h-rows, 32 chans x 32 w.
// Reads: float4 per thread per row -- thread (c = tid>>3, w4 = tid&7) loads
// plane[c][h][wt*32 + 4*w4 .. +3]; warp = 4 channels x 128B coalesced.
// Smem + write phase identical to R8: 128B contiguous scratch store per warp.
// ---------------------------------------------------------------------------
template<int P0, int P1, int P2, int ROWS>
__device__ __forceinline__ void transpose_body(const float* __restrict__ planes,
                                               int tb) {
    __shared__ float t[ROWS][32][33];

    const int tid = threadIdx.x;
    const int c   = tid >> 3;                     // channel 0..31
    const int w4  = tid & 7;                      // float4 slot 0..7

    constexpr int HG = RES / ROWS;
    const int wt = tb & 15;
    const int hb = ((tb >> 4) % HG) * ROWS;
    const int pj = tb / (16 * HG);                // 0..2
    const int p  = (pj == 0) ? P0 : (pj == 1) ? P1 : P2;

    const size_t cs = (size_t)RES * RES;
    const float* __restrict__ src =
        planes + ((size_t)p * FEAT + c) * cs + (size_t)hb * RES + (wt * 32 + 4 * w4);

    // Stage: ROWS independent 16B loads back-to-back.
    float4 v[ROWS];
    #pragma unroll
    for (int r = 0; r < ROWS; ++r)
        v[r] = __ldcs((const float4*)(src + (size_t)r * RES));

    #pragma unroll
    for (int r = 0; r < ROWS; ++r) {
        t[r][c][4 * w4 + 0] = v[r].x;
        t[r][c][4 * w4 + 1] = v[r].y;
        t[r][c][4 * w4 + 2] = v[r].z;
        t[r][c][4 * w4 + 3] = v[r].w;
    }
    __syncthreads();

    const int tx   = tid & 31;
    const int ty   = tid >> 5;                    // 0..7
    const int pair = tx & 15;
    #pragma unroll
    for (int r = 0; r < ROWS; ++r) {
        #pragma unroll
        for (int j = 0; j < 2; ++j) {
            const int wl  = (ty + 8 * j) * 2 + (tx >> 4);   // 0..31
            const int col = wt * 32 + wl;
            g_scratch[(((p * RES + (hb + r)) * RES) + col) * PAIRS + pair] =
                __floats2half2_rn(t[r][2 * pair][wl], t[r][2 * pair + 1][wl]);
        }
    }
}

// ---------------------------------------------------------------------------
// Sample body: warp covers 8 points, 2 points/thread, 24 batched 8B gathers.
// G=0: planes {0,1,3} -> space. G=1: {2,4,5} -> spacetime.
// ---------------------------------------------------------------------------
template<int G>
__device__ __forceinline__ void sample_body(const float* __restrict__ pts,
                                            const float* __restrict__ tim,
                                            float* __restrict__ out,
                                            int N, int sbid) {
    const int gwarp = (sbid * 256 + (int)threadIdx.x) >> 5;
    const int lane  = threadIdx.x & 31;
    const int sub   = lane & 7;
    const int k     = lane >> 3;

    const int wpt = gwarp * 8;
    if (wpt >= N) return;

    int ptv[2];
    ptv[0] = wpt + k;
    ptv[1] = wpt + k + 4;

    const __half2* __restrict__ sc = g_scratch;

    int   a00[2][3], a01[2][3], a10[2][3], a11[2][3];
    float w00[2][3], w01[2][3], w10[2][3], w11[2][3];
    bool  valid[2];

    #pragma unroll
    for (int q = 0; q < 2; ++q) {
        const int pt = ptv[q];
        valid[q] = (pt < N);
        const int ps = valid[q] ? pt : 0;

        const float inv_b = 1.0f / 1.6f;
        const float dx = pts[ps * 3 + 0] * inv_b;
        const float dy = pts[ps * 3 + 1] * inv_b;
        const float dz = pts[ps * 3 + 2] * inv_b;

        float cx[3], cy[3];
        int pid[3];
        if (G == 0) {
            pid[0] = 0; cx[0] = dx; cy[0] = dy;
            pid[1] = 1; cx[1] = dx; cy[1] = dz;
            pid[2] = 3; cx[2] = dy; cy[2] = dz;
        } else {
            const float dt = tim[ps] * 2.0f - 1.0f;
            pid[0] = 2; cx[0] = dt; cy[0] = dx;
            pid[1] = 4; cx[1] = dt; cy[1] = dy;
            pid[2] = 5; cx[2] = dt; cy[2] = dz;
        }

        #pragma unroll
        for (int i = 0; i < 3; ++i) {
            const float x = fminf(fmaxf((cx[i] + 1.0f) * 0.5f * (float)(RES - 1), 0.0f), (float)(RES - 1));
            const float y = fminf(fmaxf((cy[i] + 1.0f) * 0.5f * (float)(RES - 1), 0.0f), (float)(RES - 1));
            const float x0f = floorf(x);
            const float y0f = floorf(y);
            const int x0 = (int)x0f;
            const int y0 = (int)y0f;
            const int x1 = min(x0 + 1, RES - 1);
            const int y1 = min(y0 + 1, RES - 1);
            const float wx = x - x0f;
            const float wy = y - y0f;

            const int pbase = pid[i] * (RES * RES * PAIRS) + 2 * sub;
            a00[q][i] = pbase + (y0 * RES + x0) * PAIRS;
            a01[q][i] = pbase + (y0 * RES + x1) * PAIRS;
            a10[q][i] = pbase + (y1 * RES + x0) * PAIRS;
            a11[q][i] = pbase + (y1 * RES + x1) * PAIRS;
            w00[q][i] = (1.0f - wx) * (1.0f - wy);
            w01[q][i] = wx * (1.0f - wy);
            w10[q][i] = (1.0f - wx) * wy;
            w11[q][i] = wx * wy;
        }
    }

    uint2 c00[2][3], c01[2][3], c10[2][3], c11[2][3];
    #pragma unroll
    for (int q = 0; q < 2; ++q) {
        #pragma unroll
        for (int i = 0; i < 3; ++i) {
            c00[q][i] = __ldg((const uint2*)(sc + a00[q][i]));
            c01[q][i] = __ldg((const uint2*)(sc + a01[q][i]));
            c10[q][i] = __ldg((const uint2*)(sc + a10[q][i]));
            c11[q][i] = __ldg((const uint2*)(sc + a11[q][i]));
        }
    }

    #pragma unroll
    for (int q = 0; q < 2; ++q) {
        float f[3][4];
        #pragma unroll
        for (int i = 0; i < 3; ++i) {
            const float2 v00a = __half22float2(*(const __half2*)&c00[q][i].x);
            const float2 v00b = __half22float2(*(const __half2*)&c00[q][i].y);
            const float2 v01a = __half22float2(*(const __half2*)&c01[q][i].x);
            const float2 v01b = __half22float2(*(const __half2*)&c01[q][i].y);
            const float2 v10a = __half22float2(*(const __half2*)&c10[q][i].x);
            const float2 v10b = __half22float2(*(const __half2*)&c10[q][i].y);
            const float2 v11a = __half22float2(*(const __half2*)&c11[q][i].x);
            const float2 v11b = __half22float2(*(const __half2*)&c11[q][i].y);

            f[i][0] = v00a.x * w00[q][i] + v01a.x * w01[q][i] + v10a.x * w10[q][i] + v11a.x * w11[q][i];
            f[i][1] = v00a.y * w00[q][i] + v01a.y * w01[q][i] + v10a.y * w10[q][i] + v11a.y * w11[q][i];
            f[i][2] = v00b.x * w00[q][i] + v01b.x * w01[q][i] + v10b.x * w10[q][i] + v11b.x * w11[q][i];
            f[i][3] = v00b.y * w00[q][i] + v01b.y * w01[q][i] + v10b.y * w10[q][i] + v11b.y * w11[q][i];
        }

        float4 r;
        r.x = f[0][0] * f[1][0] * f[2][0];
        r.y = f[0][1] * f[1][1] * f[2][1];
        r.z = f[0][2] * f[1][2] * f[2][2];
        r.w = f[0][3] * f[1][3] * f[2][3];

        if (valid[q]) {
            float4* __restrict__ o = (float4*)out + (size_t)G * N * 8 + (size_t)ptv[q] * 8 + sub;
            __stcs(o, r);
        }
    }
}

// K1: transpose planes {0,1,3}, 4-row tiles.
__global__ void __launch_bounds__(256)
transpose_first_kernel(const float* __restrict__ planes) {
    transpose_body<0, 1, 3, 4>(planes, blockIdx.x);
}

// K2: role-interleaved fused kernel.
//   bid < B_SPLIT: r=bid%9; r<4 -> transpose{2,4,5} tile (bid/9)*4+r
//                           else -> sample0 block (bid/9)*5+(r-4)
//   bid >= B_SPLIT: sample0 block SB_PATTERN + (bid - B_SPLIT)
__global__ void __launch_bounds__(256)
fused_kernel(const float* __restrict__ planes,
             const float* __restrict__ pts,
             const float* __restrict__ tim,
             float* __restrict__ out,
             int N) {
    const int bid = blockIdx.x;
    if (bid < B_SPLIT) {
        const int q = bid / 9;
        const int r = bid % 9;
        if (r < 4) {
            transpose_body<2, 4, 5, 2>(planes, q * 4 + r);
        } else {
            sample_body<0>(pts, tim, out, N, q * 5 + (r - 4));
        }
    } else {
        sample_body<0>(pts, tim, out, N, SB_PATTERN + (bid - B_SPLIT));
    }
}

// K3: sample group 1.
__global__ void __launch_bounds__(256)
sample1_kernel(const float* __restrict__ pts,
               const float* __restrict__ tim,
               float* __restrict__ out,
               int N) {
    sample_body<1>(pts, tim, out, N, blockIdx.x);
}

extern "C" void kernel_launch(void* const* d_in, const int* in_sizes, int n_in,
                              void* d_out, int out_size) {
    const float* pts    = (const float*)d_in[0];
    const float* tim    = (const float*)d_in[1];
    const float* planes = (const float*)d_in[2];

    const int N = in_sizes[0] / 3;

    const int warps   = (N + 7) / 8;
    const int sblocks = (warps * 32 + 255) / 256;

    transpose_first_kernel<<<TB1, 256>>>(planes);

    int extra = sblocks - SB_PATTERN;
    if (extra < 0) extra = 0;
    fused_kernel<<<B_SPLIT + extra, 256>>>(planes, pts, tim, (float*)d_out, N);

    sample1_kernel<<<sblocks, 256>>>(pts, tim, (float*)d_out, N);
}